// round 11
// baseline (speedup 1.0000x reference)
#include <cuda_runtime.h>
#include <math_constants.h>

// Morphological opening (10x10 min then 10x10 max, SAME pad lo=4/hi=5),
// NHWC [16,512,512,8] f32. Fused single kernel (one pass, 268MB DRAM),
// vertical-first van Herk. Block = 16(h) x 32(w) x 8ch, float4 granularity,
// coalesced gmem. vs round 7: NT=288 so H1/H2/V2 are single-round (no idle
// second rounds), and all tail loads are clamped+unconditional (batched MLP)
// with predicated stores instead of serial break-chains.

#define H_   512
#define W_   512
#define TH   16
#define TW   32
#define NT   288

#define NE    25             // eroded row range (TH + 9)
#define NCB   50             // input cols covered (TW + 18)
#define NCE   41             // eroded cols with dilation halo (TW + 9)

#define BCF   (NCB * 2)      // 100 fused (col,half) B columns
#define ECF   (NCE * 2)      // 82 fused E columns
#define FCF   (TW * 2)       // 64 fused F columns

#define B_OFF 0
#define E_OFF (BCF * NE)                 // 2500
#define F_OFF 0                          // F: 64*25=1600 <= 2500, overlays B
#define SMEM_F4 (E_OFF + ECF * NE)       // 4550
#define SMEM_BYTES (SMEM_F4 * 16)        // 72,800 -> 3 blocks/SM

__device__ __forceinline__ float4 min4(float4 a, float4 b) {
    return make_float4(fminf(a.x,b.x), fminf(a.y,b.y), fminf(a.z,b.z), fminf(a.w,b.w));
}
__device__ __forceinline__ float4 max4(float4 a, float4 b) {
    return make_float4(fmaxf(a.x,b.x), fmaxf(a.y,b.y), fmaxf(a.z,b.z), fmaxf(a.w,b.w));
}
__device__ __forceinline__ int clampi(int v, int lo, int hi) {
    return min(max(v, lo), hi);
}

__global__ __launch_bounds__(NT, 3)
void opening_kernel(const float4* __restrict__ in4, float4* __restrict__ out4) {
    extern __shared__ float4 sm[];
    float4* Bs = sm + B_OFF;   // B[cF][e], cF = cb*2 + h, stride NE
    float4* Es = sm + E_OFF;   // E[cF'][e]
    float4* Fs = sm + F_OFF;   // F[cF''][e]

    const int b   = blockIdx.z;
    const int gh0 = blockIdx.y * TH;
    const int gw0 = blockIdx.x * TW;
    const int tid = threadIdx.x;

    const size_t chanBase = (size_t)b * H_ * W_ * 2;   // f4 units
    const float4 INF4  = make_float4( CUDART_INF_F,  CUDART_INF_F,  CUDART_INF_F,  CUDART_INF_F);
    const float4 NINF4 = make_float4(-CUDART_INF_F, -CUDART_INF_F, -CUDART_INF_F, -CUDART_INF_F);

    // ---- V1: vertical min fused with coalesced gmem load. 100x3 = 300. ----
    // B[cF][e] = min over input rows (gh0+e-4)+[-4,+5] at x = gw0 + (cF>>1) - 8.
    #pragma unroll 1
    for (int i = tid; i < BCF * 3; i += NT) {
        int cF  = i % BCF, seg = i / BCF;
        int e0  = seg * 9;
        int n   = (seg == 2) ? 7 : 9;           // 9+9+7 = 25
        int gx  = gw0 + (cF >> 1) - 8;
        bool colOK = ((unsigned)gx < W_);
        const float4* src = in4 + chanBase + (size_t)clampi(gx, 0, W_ - 1) * 2 + (cF & 1);
        int yBase = gh0 - 8 + e0;

        float4 x[10];
        #pragma unroll
        for (int t = 0; t < 10; t++) {
            int gy  = yBase + t;
            float4 v = src[(size_t)clampi(gy, 0, H_ - 1) * (W_ * 2)];
            x[t] = (colOK && (unsigned)gy < H_) ? v : INF4;
        }
        #pragma unroll
        for (int j = 8; j >= 0; j--) x[j] = min4(x[j], x[j+1]);
        float4 pr = x[9];
        float4* q = Bs + cF * NE + e0;
        q[0] = x[0];
        float4 y[4];
        #pragma unroll
        for (int t = 0; t < 4; t++) {
            int gy = yBase + 10 + t;
            float4 v = src[(size_t)clampi(gy, 0, H_ - 1) * (W_ * 2)];
            y[t] = (colOK && (unsigned)gy < H_) ? v : INF4;
        }
        #pragma unroll
        for (int j = 1; j <= 4; j++) {
            pr = min4(pr, y[j - 1]);
            if (j < n) q[j] = min4(x[j], pr);
        }
        #pragma unroll
        for (int t = 0; t < 4; t++) {
            int gy = yBase + 14 + t;
            float4 v = src[(size_t)clampi(gy, 0, H_ - 1) * (W_ * 2)];
            y[t] = (colOK && (unsigned)gy < H_) ? v : INF4;
        }
        #pragma unroll
        for (int j = 5; j <= 8; j++) {
            pr = min4(pr, y[j - 5]);
            if (j < n) q[j] = min4(x[j], pr);
        }
    }
    __syncthreads();

    // ---- H1: horizontal min B -> eroded E, mask -inf off-image. 250 tasks. ----
    if (tid < 25 * 2 * 5) {
        int e   = tid % NE;
        int t2  = tid / NE;        // 0..9
        int h   = t2 & 1;
        int seg = t2 >> 1;         // 0..4
        int c0  = seg * 9;
        int n   = (seg == 4) ? 5 : 9;          // 9*4+5 = 41 outputs
        const float4* row = Bs + h * NE + e;   // col cb at offset cb*2*NE
        float4 x[10];
        #pragma unroll
        for (int t = 0; t < 10; t++) x[t] = row[(c0 + t) * (2 * NE)];
        #pragma unroll
        for (int j = 8; j >= 0; j--) x[j] = min4(x[j], x[j+1]);
        float4 pr = x[9];
        bool rowOK = ((unsigned)(gh0 + e - 4) < H_);
        float4* q = Es + (c0 * 2 + h) * NE + e;
        q[0] = (rowOK && (unsigned)(gw0 + c0 - 4) < W_) ? x[0] : NINF4;
        float4 y[8];
        #pragma unroll
        for (int t = 0; t < 8; t++)
            y[t] = row[clampi(c0 + 10 + t, 0, NCB - 1) * (2 * NE)];
        #pragma unroll
        for (int j = 1; j <= 8; j++) {
            pr = min4(pr, y[j - 1]);
            if (j < n) {
                float4 v = min4(x[j], pr);
                if (!rowOK || (unsigned)(gw0 + c0 + j - 4) >= W_) v = NINF4;
                q[j * (2 * NE)] = v;
            }
        }
    }
    __syncthreads();

    // ---- H2: horizontal max E -> F. 200 tasks. ----
    if (tid < 25 * 2 * 4) {
        int e   = tid % NE;
        int t2  = tid / NE;        // 0..7
        int h   = t2 & 1;
        int seg = t2 >> 1;         // 0..3
        int c0  = seg * 9;
        int n   = (seg == 3) ? 5 : 9;          // 9*3+5 = 32 outputs
        const float4* row = Es + h * NE + e;
        float4 x[10];
        #pragma unroll
        for (int t = 0; t < 10; t++) x[t] = row[(c0 + t) * (2 * NE)];
        #pragma unroll
        for (int j = 8; j >= 0; j--) x[j] = max4(x[j], x[j+1]);
        float4 pr = x[9];
        float4* q = Fs + (c0 * 2 + h) * NE + e;
        q[0] = x[0];
        float4 y[8];
        #pragma unroll
        for (int t = 0; t < 8; t++)
            y[t] = row[clampi(c0 + 10 + t, 0, NCE - 1) * (2 * NE)];
        #pragma unroll
        for (int j = 1; j <= 8; j++) {
            pr = max4(pr, y[j - 1]);
            if (j < n) q[j * (2 * NE)] = max4(x[j], pr);
        }
    }
    __syncthreads();

    // ---- V2: vertical max F -> gmem (coalesced). 128 tasks. ----
    if (tid < FCF * 2) {
        int cF  = tid % FCF, seg = tid / FCF;
        int r0  = seg * 9;
        int n   = (seg == 1) ? 7 : 9;          // 9+7 = 16 outputs
        const float4* p = Fs + cF * NE + r0;   // stride 1 along e
        float4 x[10];
        #pragma unroll
        for (int t = 0; t < 10; t++) x[t] = p[t];
        #pragma unroll
        for (int j = 8; j >= 0; j--) x[j] = max4(x[j], x[j+1]);
        float4 pr = x[9];
        float4* q = out4 + chanBase + ((size_t)(gh0 + r0) * W_ + gw0) * 2 + cF;
        q[0] = x[0];
        float4 y[8];
        #pragma unroll
        for (int t = 0; t < 8; t++)
            y[t] = p[clampi(10 + t, 0, NE - 1 - r0)];
        #pragma unroll
        for (int j = 1; j <= 8; j++) {
            pr = max4(pr, y[j - 1]);
            if (j < n) q[(size_t)j * (W_ * 2)] = max4(x[j], pr);
        }
    }
}

extern "C" void kernel_launch(void* const* d_in, const int* in_sizes, int n_in,
                              void* d_out, int out_size) {
    const float4* in  = (const float4*)d_in[0];
    float4* out = (float4*)d_out;

    cudaFuncSetAttribute(opening_kernel,
                         cudaFuncAttributeMaxDynamicSharedMemorySize, SMEM_BYTES);

    dim3 grid(W_ / TW, H_ / TH, 16);
    opening_kernel<<<grid, NT, SMEM_BYTES>>>(in, out);
}

// round 12
// speedup vs baseline: 1.4698x; 1.4698x over previous
#include <cuda_runtime.h>
#include <math_constants.h>

// Morphological opening (10x10 min then 10x10 max, SAME pad lo=4/hi=5),
// NHWC [16,512,512,8] f32. Fused single kernel, vertical-first van Herk.
// Block = 16(h) x 32(w) x 8ch, float4, coalesced gmem, 3 blocks/SM.
// vs round 7: van Herk tail loads are batched BEFORE the prefix chain --
//  - smem stages: unconditional over-reads (land in adjacent smem arrays,
//    provably unused for stored outputs; smem padded so they stay in-bounds)
//  - V1 gmem: whole-task interior/boundary branch; interior = 18 plain LDG.
// No clamps, no per-load selects (round 11's mistake).

#define H_   512
#define W_   512
#define TH   16
#define TW   32
#define NT   256

#define NE    25             // eroded row range (TH + 9)
#define NCB   50             // input cols covered (TW + 18)
#define NCE   41             // eroded cols with dilation halo (TW + 9)

#define BCF   (NCB * 2)      // 100 fused (col,half) B columns
#define ECF   (NCE * 2)      // 82 fused E columns
#define FCF   (TW * 2)       // 64 fused F columns

#define B_OFF 0
#define E_OFF (BCF * NE)                 // 2500
#define F_OFF 0                          // F: 64*25=1600, overlays B
#define SMEM_F4 (E_OFF + ECF * NE + 200) // 4750 (+200 f4 over-read pad)
#define SMEM_BYTES (SMEM_F4 * 16)        // 76,000 -> 3 blocks/SM (231KB)

__device__ __forceinline__ float4 min4(float4 a, float4 b) {
    return make_float4(fminf(a.x,b.x), fminf(a.y,b.y), fminf(a.z,b.z), fminf(a.w,b.w));
}
__device__ __forceinline__ float4 max4(float4 a, float4 b) {
    return make_float4(fmaxf(a.x,b.x), fmaxf(a.y,b.y), fmaxf(a.z,b.z), fmaxf(a.w,b.w));
}

__global__ __launch_bounds__(NT, 3)
void opening_kernel(const float4* __restrict__ in4, float4* __restrict__ out4) {
    extern __shared__ float4 sm[];
    float4* Bs = sm + B_OFF;   // B[cF][e], cF = cb*2 + h
    float4* Es = sm + E_OFF;   // E[cF'][e]
    float4* Fs = sm + F_OFF;   // F[cF''][e]

    const int b   = blockIdx.z;
    const int gh0 = blockIdx.y * TH;
    const int gw0 = blockIdx.x * TW;
    const int tid = threadIdx.x;

    const size_t chanBase = (size_t)b * H_ * W_ * 2;   // f4 units
    const float4 INF4  = make_float4( CUDART_INF_F,  CUDART_INF_F,  CUDART_INF_F,  CUDART_INF_F);
    const float4 NINF4 = make_float4(-CUDART_INF_F, -CUDART_INF_F, -CUDART_INF_F, -CUDART_INF_F);

    // ---- V1: vertical min fused with coalesced gmem load. 100x3 = 300. ----
    // B[cF][e] = min over input rows (gh0-8+e) .. (gh0+1+e), x = gw0+(cF>>1)-8.
    #pragma unroll 1
    for (int i = tid; i < BCF * 3; i += NT) {
        int cF  = i % BCF, seg = i / BCF;
        int e0  = seg * 9;
        int n   = (seg == 2) ? 7 : 9;           // 9+9+7 = 25
        int gx  = gw0 + (cF >> 1) - 8;
        int yBase = gh0 - 8 + e0;
        float4* q = Bs + cF * NE + e0;

        if ((unsigned)gx >= W_) {
            // whole column off-image: erosion window all +inf
            #pragma unroll
            for (int j = 0; j < 9; j++) if (j < n) q[j] = INF4;
        } else {
            const float4* src = in4 + chanBase + (size_t)gx * 2 + (cF & 1);
            float4 x[10], y0[4], y1[4];
            if (yBase >= 0 && yBase <= H_ - 18) {
                // interior: all 18 rows valid -- plain batched loads
                #pragma unroll
                for (int t = 0; t < 10; t++) x[t]  = src[(size_t)(yBase + t)      * (W_ * 2)];
                #pragma unroll
                for (int t = 0; t < 4;  t++) y0[t] = src[(size_t)(yBase + 10 + t) * (W_ * 2)];
                #pragma unroll
                for (int t = 0; t < 4;  t++) y1[t] = src[(size_t)(yBase + 14 + t) * (W_ * 2)];
            } else {
                #pragma unroll
                for (int t = 0; t < 10; t++) {
                    int gy = yBase + t;  x[t] = INF4;
                    if ((unsigned)gy < H_) x[t] = src[(size_t)gy * (W_ * 2)];
                }
                #pragma unroll
                for (int t = 0; t < 4; t++) {
                    int gy = yBase + 10 + t;  y0[t] = INF4;
                    if ((unsigned)gy < H_) y0[t] = src[(size_t)gy * (W_ * 2)];
                }
                #pragma unroll
                for (int t = 0; t < 4; t++) {
                    int gy = yBase + 14 + t;  y1[t] = INF4;
                    if ((unsigned)gy < H_) y1[t] = src[(size_t)gy * (W_ * 2)];
                }
            }
            #pragma unroll
            for (int j = 8; j >= 0; j--) x[j] = min4(x[j], x[j+1]);
            float4 pr = x[9];
            q[0] = x[0];
            #pragma unroll
            for (int j = 1; j <= 4; j++) {
                pr = min4(pr, y0[j - 1]);
                if (j < n) q[j] = min4(x[j], pr);
            }
            #pragma unroll
            for (int j = 5; j <= 8; j++) {
                pr = min4(pr, y1[j - 5]);
                if (j < n) q[j] = min4(x[j], pr);
            }
        }
    }
    __syncthreads();

    // ---- H1: horizontal min B -> eroded E, mask -inf off-image. 250 tasks. ----
    if (tid < 25 * 2 * 5) {
        int e   = tid % NE;
        int t2  = tid / NE;        // 0..9
        int h   = t2 & 1;
        int seg = t2 >> 1;         // 0..4
        int c0  = seg * 9;
        int n   = (seg == 4) ? 5 : 9;          // 41 outputs
        const float4* row = Bs + h * NE + e;   // col cb at offset cb*2*NE
        float4 x[10];
        #pragma unroll
        for (int t = 0; t < 10; t++) x[t] = row[(c0 + t) * (2 * NE)];
        #pragma unroll
        for (int j = 8; j >= 0; j--) x[j] = min4(x[j], x[j+1]);
        float4 y[8];
        #pragma unroll
        for (int t = 0; t < 8; t++) y[t] = row[(c0 + 10 + t) * (2 * NE)]; // over-read safe
        float4 pr = x[9];
        bool rowOK = ((unsigned)(gh0 + e - 4) < H_);
        float4* q = Es + (c0 * 2 + h) * NE + e;
        q[0] = (rowOK && (unsigned)(gw0 + c0 - 4) < W_) ? x[0] : NINF4;
        #pragma unroll
        for (int j = 1; j <= 8; j++) {
            pr = min4(pr, y[j - 1]);
            if (j < n) {
                float4 v = min4(x[j], pr);
                if (!rowOK || (unsigned)(gw0 + c0 + j - 4) >= W_) v = NINF4;
                q[j * (2 * NE)] = v;
            }
        }
    }
    __syncthreads();

    // ---- H2: horizontal max E -> F. 200 tasks. ----
    if (tid < 25 * 2 * 4) {
        int e   = tid % NE;
        int t2  = tid / NE;        // 0..7
        int h   = t2 & 1;
        int seg = t2 >> 1;         // 0..3
        int c0  = seg * 9;
        int n   = (seg == 3) ? 5 : 9;          // 32 outputs
        const float4* row = Es + h * NE + e;
        float4 x[10];
        #pragma unroll
        for (int t = 0; t < 10; t++) x[t] = row[(c0 + t) * (2 * NE)];
        #pragma unroll
        for (int j = 8; j >= 0; j--) x[j] = max4(x[j], x[j+1]);
        float4 y[8];
        #pragma unroll
        for (int t = 0; t < 8; t++) y[t] = row[(c0 + 10 + t) * (2 * NE)]; // over-read safe
        float4 pr = x[9];
        float4* q = Fs + (c0 * 2 + h) * NE + e;
        q[0] = x[0];
        #pragma unroll
        for (int j = 1; j <= 8; j++) {
            pr = max4(pr, y[j - 1]);
            if (j < n) q[j * (2 * NE)] = max4(x[j], pr);
        }
    }
    __syncthreads();

    // ---- V2: vertical max F -> gmem (coalesced). 128 tasks. ----
    if (tid < FCF * 2) {
        int cF  = tid % FCF, seg = tid / FCF;
        int r0  = seg * 9;
        int n   = (seg == 1) ? 7 : 9;          // 16 outputs
        const float4* p = Fs + cF * NE + r0;   // stride 1 along e
        float4 x[10];
        #pragma unroll
        for (int t = 0; t < 10; t++) x[t] = p[t];
        #pragma unroll
        for (int j = 8; j >= 0; j--) x[j] = max4(x[j], x[j+1]);
        float4 y[8];
        #pragma unroll
        for (int t = 0; t < 8; t++) y[t] = p[10 + t];   // over-read safe
        float4 pr = x[9];
        float4* q = out4 + chanBase + ((size_t)(gh0 + r0) * W_ + gw0) * 2 + cF;
        q[0] = x[0];
        #pragma unroll
        for (int j = 1; j <= 8; j++) {
            pr = max4(pr, y[j - 1]);
            if (j < n) q[(size_t)j * (W_ * 2)] = max4(x[j], pr);
        }
    }
}

extern "C" void kernel_launch(void* const* d_in, const int* in_sizes, int n_in,
                              void* d_out, int out_size) {
    const float4* in  = (const float4*)d_in[0];
    float4* out = (float4*)d_out;

    cudaFuncSetAttribute(opening_kernel,
                         cudaFuncAttributeMaxDynamicSharedMemorySize, SMEM_BYTES);

    dim3 grid(W_ / TW, H_ / TH, 16);
    opening_kernel<<<grid, NT, SMEM_BYTES>>>(in, out);
}